// round 14
// baseline (speedup 1.0000x reference)
#include <cuda_runtime.h>
#include <cuda_fp16.h>
#include <math.h>
#include <stdint.h>

#define TT   8192
#define CD   1024
#define FD   1024
#define NE   8
#define HWD  4096
#define BD   2
#define NENT (TT*2)
#define NCTA 296   // 148 SMs x 2 CTAs

// ---------------- scratch (16B-aligned for cp.async / vector ld-st) ----------------
__device__ __align__(16) __half g_Xf [TT * CD];
__device__ __align__(16) __half g_W1 [NE * FD * CD];
__device__ __align__(16) __half g_W3 [NE * FD * CD];
__device__ __align__(16) __half g_W2 [NE * CD * FD];
__device__ __align__(16) __half g_Hf [NENT * FD];
__device__ __align__(16) __half g_Yf [NENT * CD];
__device__ __align__(16) float  g_wt [NENT];
__device__ int  g_cnt[NE];
__device__ __align__(16) int  g_list[NE * TT];
__device__ __align__(16) int  g_tile_e[160];
__device__ __align__(16) int  g_tile_m0[160];
__device__ int  g_ntiles;
__device__ int  g_ticket1;
__device__ int  g_ticket2;

// ---------------- helpers ----------------
__device__ __forceinline__ uint32_t smem_u32(const void* p) {
    uint32_t a;
    asm("{ .reg .u64 t; cvta.to.shared.u64 t, %1; cvt.u32.u64 %0, t; }" : "=r"(a) : "l"(p));
    return a;
}
__device__ __forceinline__ void cp16(uint32_t dst, const void* src) {
    asm volatile("cp.async.cg.shared.global [%0], [%1], 16;" :: "r"(dst), "l"(src) : "memory");
}
#define CP_COMMIT() asm volatile("cp.async.commit_group;" ::: "memory")
#define CP_WAIT1()  asm volatile("cp.async.wait_group 1;" ::: "memory")
#define CP_WAIT0()  asm volatile("cp.async.wait_group 0;" ::: "memory")
#define PIPE_WAIT(ch) do { if ((ch) < 15) { CP_WAIT1(); } else { CP_WAIT0(); } } while (0)

// SW128 swizzle
__device__ __forceinline__ uint32_t sw128(uint32_t o) { return o ^ ((o >> 3) & 0x70); }

__device__ __forceinline__ void ldsm4(uint32_t* r, uint32_t a) {
    asm volatile("ldmatrix.sync.aligned.m8n8.x4.shared.b16 {%0,%1,%2,%3}, [%4];"
        : "=r"(r[0]), "=r"(r[1]), "=r"(r[2]), "=r"(r[3]) : "r"(a));
}
__device__ __forceinline__ void mma_f16(float* c, const uint32_t* a, const uint32_t* b) {
    asm volatile(
        "mma.sync.aligned.m16n8k16.row.col.f32.f16.f16.f32 "
        "{%0,%1,%2,%3}, {%4,%5,%6,%7}, {%8,%9}, {%0,%1,%2,%3};"
        : "+f"(c[0]), "+f"(c[1]), "+f"(c[2]), "+f"(c[3])
        : "r"(a[0]), "r"(a[1]), "r"(a[2]), "r"(a[3]), "r"(b[0]), "r"(b[1]));
}

// smem stage layout (bytes), K-chunk 64, stage 32768, THREE stages
#define A_OFF 0
#define B_OFF 16384
#define STG   32768
#define DSM   (3*STG)   // 98304

// ------------------------------------------------------------------
__global__ void reset_kernel() {
    int t = threadIdx.x;
    if (t < NE) g_cnt[t] = 0;
    if (t == 8) g_ticket1 = 0;
    if (t == 9) g_ticket2 = 0;
}

// NCHW -> [T,C] fp16 plane only
__global__ __launch_bounds__(256) void transpose_pack_kernel(const float* __restrict__ hs) {
    __shared__ float tile[32][33];
    const int b = blockIdx.z, c0 = blockIdx.y * 32, s0 = blockIdx.x * 32;
    const int tx = threadIdx.x, ty = threadIdx.y;
#pragma unroll
    for (int r = 0; r < 4; r++) {
        int cc = ty + r * 8;
        tile[cc][tx] = hs[((size_t)(b * CD + c0 + cc)) * HWD + s0 + tx];
    }
    __syncthreads();
#pragma unroll
    for (int r = 0; r < 4; r++) {
        int ss = ty + r * 8;
        size_t idx = ((size_t)(b * HWD + s0 + ss)) * CD + c0 + tx;
        g_Xf[idx] = __float2half_rn(tile[tx][ss]);
    }
}

// all three weights, single fp16 plane; blockIdx.y selects the array
__global__ __launch_bounds__(256) void prep_all(const float* __restrict__ w1,
                                                const float* __restrict__ w3,
                                                const float* __restrict__ w2) {
    const int which = blockIdx.y;
    const float* s = (which == 0) ? w1 : (which == 1) ? w3 : w2;
    __half* dh = (which == 0) ? g_W1 : (which == 1) ? g_W3 : g_W2;
    size_t i = ((size_t)blockIdx.x * 256 + threadIdx.x) * 4;
    float4 v = *(const float4*)(s + i);
    __half hbuf[4] = { __float2half_rn(v.x), __float2half_rn(v.y),
                       __float2half_rn(v.z), __float2half_rn(v.w) };
    *(uint2*)(dh + i) = *(uint2*)hbuf;
}

// router v3: NCHW-direct, 32 tokens/block, warp = 128-channel slice, fp32 math
__global__ __launch_bounds__(256) void router_kernel(const float* __restrict__ hs,
                                                     const float* __restrict__ gw) {
    __shared__ float sg[NE * CD];
    __shared__ float part[8][32][NE];
    const int tid = threadIdx.x;
    for (int i = tid; i < NE * CD; i += 256) sg[i] = gw[i];
    __syncthreads();

    const int warp = tid >> 5, lane = tid & 31;
    const int tok0 = blockIdx.x * 32;
    const int b = tok0 >> 12;
    const int s = (tok0 & (HWD - 1)) + lane;
    const float* src = hs + ((size_t)b * CD + warp * 128) * HWD + s;
    const float* gq  = sg + warp * 128;

    float acc[NE];
#pragma unroll
    for (int e = 0; e < NE; e++) acc[e] = 0.f;
    for (int c = 0; c < 128; c += 4) {
        float x0 = src[(size_t)(c + 0) * HWD];
        float x1 = src[(size_t)(c + 1) * HWD];
        float x2 = src[(size_t)(c + 2) * HWD];
        float x3 = src[(size_t)(c + 3) * HWD];
#pragma unroll
        for (int e = 0; e < NE; e++) {
            acc[e] = fmaf(x0, gq[e * CD + c + 0], acc[e]);
            acc[e] = fmaf(x1, gq[e * CD + c + 1], acc[e]);
            acc[e] = fmaf(x2, gq[e * CD + c + 2], acc[e]);
            acc[e] = fmaf(x3, gq[e * CD + c + 3], acc[e]);
        }
    }
#pragma unroll
    for (int e = 0; e < NE; e++) part[warp][lane][e] = acc[e];
    __syncthreads();

    if (tid < 32) {
        float p[NE];
#pragma unroll
        for (int e = 0; e < NE; e++) {
            float v = 0.f;
#pragma unroll
            for (int w = 0; w < 8; w++) v += part[w][tid][e];
            p[e] = v;
        }
        float mx = p[0];
#pragma unroll
        for (int e = 1; e < NE; e++) mx = fmaxf(mx, p[e]);
#pragma unroll
        for (int e = 0; e < NE; e++) p[e] = expf(p[e] - mx);
        int i0 = 0; float b0 = p[0];
#pragma unroll
        for (int e = 1; e < NE; e++) if (p[e] > b0) { b0 = p[e]; i0 = e; }
        int i1 = (i0 == 0) ? 1 : 0; float b1 = p[i1];
#pragma unroll
        for (int e = 0; e < NE; e++)
            if (e != i0 && p[e] > b1) { b1 = p[e]; i1 = e; }
        float inv = 1.f / (b0 + b1);
        const int t = tok0 + tid;
        g_wt[t * 2 + 0] = b0 * inv;
        g_wt[t * 2 + 1] = b1 * inv;
        int p0 = atomicAdd(&g_cnt[i0], 1);
        g_list[i0 * TT + p0] = t * 2 + 0;
        int p1 = atomicAdd(&g_cnt[i1], 1);
        g_list[i1 * TT + p1] = t * 2 + 1;
    }
}

__global__ void schedule_kernel() {
    if (threadIdx.x == 0) {
        int nt = 0;
        for (int e = 0; e < NE; e++) {
            int c = g_cnt[e];
            for (int m0 = 0; m0 < c; m0 += 128) { g_tile_e[nt] = e; g_tile_m0[nt] = m0; nt++; }
        }
        g_ntiles = nt;
    }
}

// ---- tile loaders (cp.async), K-chunk 64, SW128 swizzled smem ----
__device__ __forceinline__ void load_A(uint32_t sbase, const __half* __restrict__ src0,
                                       int kstride, const int* asrc, int k0, int tid) {
#pragma unroll
    for (int i = 0; i < 4; i++) {
        int seg = tid + i * 256;
        int row = seg >> 3, q = seg & 7;
        const __half* src = src0 + (size_t)asrc[row] * kstride + k0 + q * 8;
        cp16(sbase + A_OFF + sw128((uint32_t)(row * 128 + q * 16)), src);
    }
}
__device__ __forceinline__ void load_B1(uint32_t sbase, int e, int n0, int k0, int tid) {
#pragma unroll
    for (int i = 0; i < 4; i++) {
        int seg = tid + i * 256;
        int mat = seg >> 9;
        int rem = seg & 511;
        int row = rem >> 3, q = rem & 7;
        const __half* base = mat ? g_W3 : g_W1;
        const __half* src = base + ((size_t)e * FD + n0 + row) * CD + k0 + q * 8;
        cp16(sbase + B_OFF + mat * 8192 + sw128((uint32_t)(row * 128 + q * 16)), src);
    }
}
__device__ __forceinline__ void load_B2(uint32_t sbase, int e, int n0, int k0, int tid) {
#pragma unroll
    for (int i = 0; i < 4; i++) {
        int seg = tid + i * 256;
        int row = (seg & 1023) >> 3, q = seg & 7;
        const __half* src = g_W2 + ((size_t)e * CD + n0 + row) * FD + k0 + q * 8;
        cp16(sbase + B_OFF + sw128((uint32_t)(row * 128 + q * 16)), src);
    }
}

// ---- warp compute for one 64-k chunk: m32 x n64, single plane ----
__device__ __forceinline__ void chunk_mma(uint32_t sbase, int bOffBase, int bRowBase,
                                          int mb, int lane, float acc[2][8][4]) {
    const int arow = lane & 15, akoff = ((lane >> 4) & 1) * 8;
    const int brow = ((lane >> 4) & 1) * 8 + (lane & 7);
    const int bkoff = ((lane >> 3) & 1) * 8;
#pragma unroll
    for (int kb = 0; kb < 64; kb += 16) {
        uint32_t a[2][4];
#pragma unroll
        for (int mi = 0; mi < 2; mi++) {
            uint32_t off = sw128((uint32_t)((mb + mi * 16 + arow) * 128 + (kb + akoff) * 2));
            ldsm4(a[mi], sbase + A_OFF + off);
        }
        uint32_t bf[8][2];
#pragma unroll
        for (int n4 = 0; n4 < 4; n4++) {
            uint32_t off = sw128((uint32_t)((bRowBase + n4 * 16 + brow) * 128 + (kb + bkoff) * 2));
            uint32_t t[4];
            ldsm4(t, sbase + bOffBase + off);
            bf[2*n4][0]=t[0]; bf[2*n4][1]=t[1]; bf[2*n4+1][0]=t[2]; bf[2*n4+1][1]=t[3];
        }
#pragma unroll
        for (int mi = 0; mi < 2; mi++)
#pragma unroll
            for (int ni = 0; ni < 8; ni++)
                mma_f16(acc[mi][ni], a[mi], bf[ni]);
    }
}

// ------------------------------------------------------------------
// Persistent GEMM1: ticket loop over (mt, nt) tiles, n-fastest for A/L2 reuse
__global__ __launch_bounds__(256, 2) void gemm1_mma() {
    extern __shared__ char dsm[];
    __shared__ int rows[128];
    __shared__ int asrc[128];
    __shared__ int s_tile;

    const int tid = threadIdx.x, warp = tid >> 5, lane = tid & 31;
    const uint32_t sb = smem_u32(dsm);
    const int mb = (warp & 3) * 32;
    const bool isW3 = warp >= 4;
    const int bOffBase = B_OFF + (isW3 ? 8192 : 0);

    while (true) {
        if (tid == 0) s_tile = atomicAdd(&g_ticket1, 1);
        __syncthreads();
        const int t = s_tile;
        if (t >= g_ntiles * 16) break;
        const int mt = t >> 4, ntile = t & 15;
        const int e  = g_tile_e[mt];
        const int m0 = g_tile_m0[mt];
        const int ne = g_cnt[e];
        const int n0 = ntile * 64;

        if (tid < 128) {
            int i = m0 + tid;
            int ic = (i < ne) ? i : ne - 1;
            int entry = g_list[e * TT + ic];
            rows[tid] = (i < ne) ? entry : -1;
            asrc[tid] = entry >> 1;
        }
        __syncthreads();

        float acc[2][8][4];
#pragma unroll
        for (int i = 0; i < 2; i++)
#pragma unroll
            for (int j = 0; j < 8; j++)
#pragma unroll
                for (int q = 0; q < 4; q++) acc[i][j][q] = 0.f;

#pragma unroll
        for (int pf = 0; pf < 2; pf++) {
            load_A(sb + pf * STG, g_Xf, CD, asrc, pf * 64, tid);
            load_B1(sb + pf * STG, e, n0, pf * 64, tid);
            CP_COMMIT();
        }
        for (int ch = 0; ch < 16; ch++) {
            PIPE_WAIT(ch);
            __syncthreads();
            if (ch + 2 < 16) {
                uint32_t nb = sb + ((ch + 2) % 3) * STG;
                load_A(nb, g_Xf, CD, asrc, (ch + 2) * 64, tid);
                load_B1(nb, e, n0, (ch + 2) * 64, tid);
                CP_COMMIT();
            }
            chunk_mma(sb + (ch % 3) * STG, bOffBase, 0, mb, lane, acc);
        }
        __syncthreads();

        // epilogue: exchange P1/P3 via smem, gelu*mul, store H fp16
        float* P1 = (float*)dsm;
        float* P3 = (float*)(dsm + 33792);
        float* myP = isW3 ? P3 : P1;
#pragma unroll
        for (int mi = 0; mi < 2; mi++)
#pragma unroll
            for (int ni = 0; ni < 8; ni++) {
                int m = mb + mi * 16 + (lane >> 2);
                int n = ni * 8 + (lane & 3) * 2;
                myP[m * 66 + n]       = acc[mi][ni][0];
                myP[m * 66 + n + 1]   = acc[mi][ni][1];
                myP[(m+8) * 66 + n]   = acc[mi][ni][2];
                myP[(m+8) * 66 + n+1] = acc[mi][ni][3];
            }
        __syncthreads();
        for (int idx = tid; idx < 128 * 64; idx += 256) {
            int m = idx >> 6, n = idx & 63;
            int entry = rows[m];
            if (entry < 0) continue;
            float d1 = P1[m * 66 + n];
            float d3 = P3[m * 66 + n];
            float gl = 0.5f * d1 * (1.f + erff(d1 * 0.70710678118654752f)) * d3;
            g_Hf[(size_t)entry * FD + n0 + n] = __float2half_rn(gl);
        }
        // loop-top __syncthreads orders these reads vs next tile's smem writes
    }
}

// Persistent GEMM2: ticket loop, n-fastest
__global__ __launch_bounds__(256, 2) void gemm2_mma() {
    extern __shared__ char dsm[];
    __shared__ int rows[128];
    __shared__ int asrc[128];
    __shared__ float wts[128];
    __shared__ int s_tile;

    const int tid = threadIdx.x, warp = tid >> 5, lane = tid & 31;
    const uint32_t sb = smem_u32(dsm);
    const int mb = (warp >> 1) * 32;
    const int nb = (warp & 1) * 64;

    while (true) {
        if (tid == 0) s_tile = atomicAdd(&g_ticket2, 1);
        __syncthreads();
        const int t = s_tile;
        if (t >= g_ntiles * 8) break;
        const int mt = t >> 3, ntile = t & 7;
        const int e  = g_tile_e[mt];
        const int m0 = g_tile_m0[mt];
        const int ne = g_cnt[e];
        const int n0 = ntile * 128;

        if (tid < 128) {
            int i = m0 + tid;
            int ic = (i < ne) ? i : ne - 1;
            int entry = g_list[e * TT + ic];
            rows[tid] = (i < ne) ? entry : -1;
            asrc[tid] = entry;
            wts[tid] = (i < ne) ? g_wt[entry] : 0.f;
        }
        __syncthreads();

        float acc[2][8][4];
#pragma unroll
        for (int i = 0; i < 2; i++)
#pragma unroll
            for (int j = 0; j < 8; j++)
#pragma unroll
                for (int q = 0; q < 4; q++) acc[i][j][q] = 0.f;

#pragma unroll
        for (int pf = 0; pf < 2; pf++) {
            load_A(sb + pf * STG, g_Hf, FD, asrc, pf * 64, tid);
            load_B2(sb + pf * STG, e, n0, pf * 64, tid);
            CP_COMMIT();
        }
        for (int ch = 0; ch < 16; ch++) {
            PIPE_WAIT(ch);
            __syncthreads();
            if (ch + 2 < 16) {
                uint32_t nbuf = sb + ((ch + 2) % 3) * STG;
                load_A(nbuf, g_Hf, FD, asrc, (ch + 2) * 64, tid);
                load_B2(nbuf, e, n0, (ch + 2) * 64, tid);
                CP_COMMIT();
            }
            chunk_mma(sb + (ch % 3) * STG, B_OFF, nb, mb, lane, acc);
        }

        // epilogue: scale by routing weight, store Y fp16 (registers -> global, no smem)
#pragma unroll
        for (int mi = 0; mi < 2; mi++) {
            int mB = mb + mi * 16 + (lane >> 2);
#pragma unroll
            for (int half = 0; half < 2; half++) {
                int m = mB + half * 8;
                int entry = rows[m];
                if (entry < 0) continue;
                float w = wts[m];
                __half* yr = g_Yf + (size_t)entry * CD + n0 + nb;
#pragma unroll
                for (int ni = 0; ni < 8; ni++) {
                    int n = ni * 8 + (lane & 3) * 2;
                    *(__half2*)(yr + n) = __floats2half2_rn(w * acc[mi][ni][half * 2],
                                                            w * acc[mi][ni][half * 2 + 1]);
                }
            }
        }
        __syncthreads();  // rows/wts stable until all warps done reading
    }
}

// sum two slots (fp16), transpose back to NCHW fp32
__global__ __launch_bounds__(256) void combine_out_kernel(float* __restrict__ out) {
    __shared__ float tile[32][33];
    const int b = blockIdx.z, c0 = blockIdx.y * 32, s0 = blockIdx.x * 32;
    const int tx = threadIdx.x, ty = threadIdx.y;
#pragma unroll
    for (int r = 0; r < 4; r++) {
        int ss = ty + r * 8;
        size_t t2 = (size_t)(b * HWD + s0 + ss) * 2;
        tile[ss][tx] = __half2float(g_Yf[t2 * CD + c0 + tx]) +
                       __half2float(g_Yf[(t2 + 1) * CD + c0 + tx]);
    }
    __syncthreads();
#pragma unroll
    for (int r = 0; r < 4; r++) {
        int cc = ty + r * 8;
        out[((size_t)(b * CD + c0 + cc)) * HWD + s0 + tx] = tile[tx][cc];
    }
}

// ------------------------------------------------------------------
extern "C" void kernel_launch(void* const* d_in, const int* in_sizes, int n_in,
                              void* d_out, int out_size) {
    const float* hs   = (const float*)d_in[0];
    const float* gate = (const float*)d_in[1];
    const float* w1   = (const float*)d_in[2];
    const float* w2   = (const float*)d_in[3];
    const float* w3   = (const float*)d_in[4];
    float* out = (float*)d_out;

    cudaFuncSetAttribute(gemm1_mma, cudaFuncAttributeMaxDynamicSharedMemorySize, DSM);
    cudaFuncSetAttribute(gemm2_mma, cudaFuncAttributeMaxDynamicSharedMemorySize, DSM);

    reset_kernel<<<1, 32>>>();
    router_kernel<<<TT / 32, 256>>>(hs, gate);
    transpose_pack_kernel<<<dim3(HWD / 32, CD / 32, BD), dim3(32, 8)>>>(hs);
    prep_all<<<dim3(NE * FD * CD / 4 / 256, 3), 256>>>(w1, w3, w2);
    schedule_kernel<<<1, 32>>>();
    gemm1_mma<<<NCTA, 256, DSM>>>();
    gemm2_mma<<<NCTA, 256, DSM>>>();
    combine_out_kernel<<<dim3(HWD / 32, CD / 32, BD), dim3(32, 8)>>>(out);
}

// round 15
// speedup vs baseline: 1.1902x; 1.1902x over previous
#include <cuda_runtime.h>
#include <cuda_fp16.h>
#include <math.h>
#include <stdint.h>

#define TT   8192
#define CD   1024
#define FD   1024
#define NE   8
#define HWD  4096
#define BD   2
#define NENT (TT*2)

// ---------------- scratch (16B-aligned for cp.async / vector ld-st) ----------------
__device__ __align__(16) __half g_Xf [TT * CD];
__device__ __align__(16) __half g_W1 [NE * FD * CD];
__device__ __align__(16) __half g_W3 [NE * FD * CD];
__device__ __align__(16) __half g_W2 [NE * CD * FD];
__device__ __align__(16) __half g_Hf [NENT * FD];
__device__ __align__(16) __half g_Yf [NENT * CD];
__device__ __align__(16) float  g_wt [NENT];
__device__ int  g_cnt[NE];
__device__ __align__(16) int  g_list[NE * TT];

// ---------------- helpers ----------------
__device__ __forceinline__ uint32_t smem_u32(const void* p) {
    uint32_t a;
    asm("{ .reg .u64 t; cvta.to.shared.u64 t, %1; cvt.u32.u64 %0, t; }" : "=r"(a) : "l"(p));
    return a;
}
__device__ __forceinline__ void cp16(uint32_t dst, const void* src) {
    asm volatile("cp.async.cg.shared.global [%0], [%1], 16;" :: "r"(dst), "l"(src) : "memory");
}
#define CP_COMMIT() asm volatile("cp.async.commit_group;" ::: "memory")
#define CP_WAIT1()  asm volatile("cp.async.wait_group 1;" ::: "memory")
#define CP_WAIT0()  asm volatile("cp.async.wait_group 0;" ::: "memory")
#define PIPE_WAIT(ch) do { if ((ch) < 15) { CP_WAIT1(); } else { CP_WAIT0(); } } while (0)

// SW128 swizzle: conflict-free ldmatrix on 128B rows, composes with 16B cp.async
__device__ __forceinline__ uint32_t sw128(uint32_t o) { return o ^ ((o >> 3) & 0x70); }

__device__ __forceinline__ void ldsm4(uint32_t* r, uint32_t a) {
    asm volatile("ldmatrix.sync.aligned.m8n8.x4.shared.b16 {%0,%1,%2,%3}, [%4];"
        : "=r"(r[0]), "=r"(r[1]), "=r"(r[2]), "=r"(r[3]) : "r"(a));
}
__device__ __forceinline__ void mma_f16(float* c, const uint32_t* a, const uint32_t* b) {
    asm volatile(
        "mma.sync.aligned.m16n8k16.row.col.f32.f16.f16.f32 "
        "{%0,%1,%2,%3}, {%4,%5,%6,%7}, {%8,%9}, {%0,%1,%2,%3};"
        : "+f"(c[0]), "+f"(c[1]), "+f"(c[2]), "+f"(c[3])
        : "r"(a[0]), "r"(a[1]), "r"(a[2]), "r"(a[3]), "r"(b[0]), "r"(b[1]));
}

// decode m-tile index -> (expert, m0); 8-iter scan over g_cnt. Returns false if mt OOB.
__device__ __forceinline__ bool decode_tile(int mt, int& e_out, int& m0_out) {
    int acc = 0;
#pragma unroll
    for (int e = 0; e < NE; e++) {
        int nt_e = (g_cnt[e] + 127) >> 7;      // tiles for this expert
        if (mt < acc + nt_e) { e_out = e; m0_out = (mt - acc) * 128; return true; }
        acc += nt_e;
    }
    return false;
}

// smem stage layout (bytes), K-chunk 64, stage 32768, THREE stages
#define A_OFF 0
#define B_OFF 16384
#define STG   32768
#define DSM   (3*STG)   // 98304

// ------------------------------------------------------------------
__global__ void reset_kernel() { if (threadIdx.x < NE) g_cnt[threadIdx.x] = 0; }

// NCHW -> [T,C] fp16 plane only
__global__ __launch_bounds__(256) void transpose_pack_kernel(const float* __restrict__ hs) {
    __shared__ float tile[32][33];
    const int b = blockIdx.z, c0 = blockIdx.y * 32, s0 = blockIdx.x * 32;
    const int tx = threadIdx.x, ty = threadIdx.y;
#pragma unroll
    for (int r = 0; r < 4; r++) {
        int cc = ty + r * 8;
        tile[cc][tx] = hs[((size_t)(b * CD + c0 + cc)) * HWD + s0 + tx];
    }
    __syncthreads();
#pragma unroll
    for (int r = 0; r < 4; r++) {
        int ss = ty + r * 8;
        size_t idx = ((size_t)(b * HWD + s0 + ss)) * CD + c0 + tx;
        g_Xf[idx] = __float2half_rn(tile[tx][ss]);
    }
}

// all three weights, single fp16 plane; blockIdx.y selects the array
__global__ __launch_bounds__(256) void prep_all(const float* __restrict__ w1,
                                                const float* __restrict__ w3,
                                                const float* __restrict__ w2) {
    const int which = blockIdx.y;
    const float* s = (which == 0) ? w1 : (which == 1) ? w3 : w2;
    __half* dh = (which == 0) ? g_W1 : (which == 1) ? g_W3 : g_W2;
    size_t i = ((size_t)blockIdx.x * 256 + threadIdx.x) * 4;
    float4 v = *(const float4*)(s + i);
    __half hbuf[4] = { __float2half_rn(v.x), __float2half_rn(v.y),
                       __float2half_rn(v.z), __float2half_rn(v.w) };
    *(uint2*)(dh + i) = *(uint2*)hbuf;
}

// router v3: NCHW-direct, 32 tokens/block, warp = 128-channel slice, fp32 math
__global__ __launch_bounds__(256) void router_kernel(const float* __restrict__ hs,
                                                     const float* __restrict__ gw) {
    __shared__ float sg[NE * CD];
    __shared__ float part[8][32][NE];
    const int tid = threadIdx.x;
    for (int i = tid; i < NE * CD; i += 256) sg[i] = gw[i];
    __syncthreads();

    const int warp = tid >> 5, lane = tid & 31;
    const int tok0 = blockIdx.x * 32;
    const int b = tok0 >> 12;
    const int s = (tok0 & (HWD - 1)) + lane;
    const float* src = hs + ((size_t)b * CD + warp * 128) * HWD + s;
    const float* gq  = sg + warp * 128;

    float acc[NE];
#pragma unroll
    for (int e = 0; e < NE; e++) acc[e] = 0.f;
    for (int c = 0; c < 128; c += 4) {
        float x0 = src[(size_t)(c + 0) * HWD];
        float x1 = src[(size_t)(c + 1) * HWD];
        float x2 = src[(size_t)(c + 2) * HWD];
        float x3 = src[(size_t)(c + 3) * HWD];
#pragma unroll
        for (int e = 0; e < NE; e++) {
            acc[e] = fmaf(x0, gq[e * CD + c + 0], acc[e]);
            acc[e] = fmaf(x1, gq[e * CD + c + 1], acc[e]);
            acc[e] = fmaf(x2, gq[e * CD + c + 2], acc[e]);
            acc[e] = fmaf(x3, gq[e * CD + c + 3], acc[e]);
        }
    }
#pragma unroll
    for (int e = 0; e < NE; e++) part[warp][lane][e] = acc[e];
    __syncthreads();

    if (tid < 32) {
        float p[NE];
#pragma unroll
        for (int e = 0; e < NE; e++) {
            float v = 0.f;
#pragma unroll
            for (int w = 0; w < 8; w++) v += part[w][tid][e];
            p[e] = v;
        }
        float mx = p[0];
#pragma unroll
        for (int e = 1; e < NE; e++) mx = fmaxf(mx, p[e]);
#pragma unroll
        for (int e = 0; e < NE; e++) p[e] = expf(p[e] - mx);
        int i0 = 0; float b0 = p[0];
#pragma unroll
        for (int e = 1; e < NE; e++) if (p[e] > b0) { b0 = p[e]; i0 = e; }
        int i1 = (i0 == 0) ? 1 : 0; float b1 = p[i1];
#pragma unroll
        for (int e = 0; e < NE; e++)
            if (e != i0 && p[e] > b1) { b1 = p[e]; i1 = e; }
        float inv = 1.f / (b0 + b1);
        const int t = tok0 + tid;
        g_wt[t * 2 + 0] = b0 * inv;
        g_wt[t * 2 + 1] = b1 * inv;
        int p0 = atomicAdd(&g_cnt[i0], 1);
        g_list[i0 * TT + p0] = t * 2 + 0;
        int p1 = atomicAdd(&g_cnt[i1], 1);
        g_list[i1 * TT + p1] = t * 2 + 1;
    }
}

// ---- tile loaders (cp.async), K-chunk 64, SW128 swizzled smem ----
__device__ __forceinline__ void load_A(uint32_t sbase, const __half* __restrict__ src0,
                                       int kstride, const int* asrc, int k0, int tid) {
#pragma unroll
    for (int i = 0; i < 4; i++) {
        int seg = tid + i * 256;
        int row = seg >> 3, q = seg & 7;
        const __half* src = src0 + (size_t)asrc[row] * kstride + k0 + q * 8;
        cp16(sbase + A_OFF + sw128((uint32_t)(row * 128 + q * 16)), src);
    }
}
__device__ __forceinline__ void load_B1(uint32_t sbase, int e, int n0, int k0, int tid) {
#pragma unroll
    for (int i = 0; i < 4; i++) {
        int seg = tid + i * 256;
        int mat = seg >> 9;
        int rem = seg & 511;
        int row = rem >> 3, q = rem & 7;
        const __half* base = mat ? g_W3 : g_W1;
        const __half* src = base + ((size_t)e * FD + n0 + row) * CD + k0 + q * 8;
        cp16(sbase + B_OFF + mat * 8192 + sw128((uint32_t)(row * 128 + q * 16)), src);
    }
}
__device__ __forceinline__ void load_B2(uint32_t sbase, int e, int n0, int k0, int tid) {
#pragma unroll
    for (int i = 0; i < 4; i++) {
        int seg = tid + i * 256;
        int row = (seg & 1023) >> 3, q = seg & 7;
        const __half* src = g_W2 + ((size_t)e * CD + n0 + row) * FD + k0 + q * 8;
        cp16(sbase + B_OFF + sw128((uint32_t)(row * 128 + q * 16)), src);
    }
}

// ---- warp compute for one 64-k chunk: m32 x n64, single plane ----
__device__ __forceinline__ void chunk_mma(uint32_t sbase, int bOffBase, int bRowBase,
                                          int mb, int lane, float acc[2][8][4]) {
    const int arow = lane & 15, akoff = ((lane >> 4) & 1) * 8;
    const int brow = ((lane >> 4) & 1) * 8 + (lane & 7);
    const int bkoff = ((lane >> 3) & 1) * 8;
#pragma unroll
    for (int kb = 0; kb < 64; kb += 16) {
        uint32_t a[2][4];
#pragma unroll
        for (int mi = 0; mi < 2; mi++) {
            uint32_t off = sw128((uint32_t)((mb + mi * 16 + arow) * 128 + (kb + akoff) * 2));
            ldsm4(a[mi], sbase + A_OFF + off);
        }
        uint32_t bf[8][2];
#pragma unroll
        for (int n4 = 0; n4 < 4; n4++) {
            uint32_t off = sw128((uint32_t)((bRowBase + n4 * 16 + brow) * 128 + (kb + bkoff) * 2));
            uint32_t t[4];
            ldsm4(t, sbase + bOffBase + off);
            bf[2*n4][0]=t[0]; bf[2*n4][1]=t[1]; bf[2*n4+1][0]=t[2]; bf[2*n4+1][1]=t[3];
        }
#pragma unroll
        for (int mi = 0; mi < 2; mi++)
#pragma unroll
            for (int ni = 0; ni < 8; ni++)
                mma_f16(acc[mi][ni], a[mi], bf[ni]);
    }
}

// ------------------------------------------------------------------
// GEMM1: 128 rows x 64 ffn cols; warps 0-3 -> W1, warps 4-7 -> W3
__global__ __launch_bounds__(256, 2) void gemm1_mma() {
    int e, m0;
    if (!decode_tile(blockIdx.y, e, m0)) return;
    extern __shared__ char dsm[];
    __shared__ int rows[128];
    __shared__ int asrc[128];

    const int tid = threadIdx.x, warp = tid >> 5, lane = tid & 31;
    const int ne = g_cnt[e];
    const int n0 = blockIdx.x * 64;

    if (tid < 128) {
        int i = m0 + tid;
        int ic = (i < ne) ? i : ne - 1;
        int entry = g_list[e * TT + ic];
        rows[tid] = (i < ne) ? entry : -1;
        asrc[tid] = entry >> 1;
    }
    __syncthreads();

    const uint32_t sb = smem_u32(dsm);
    const int mb = (warp & 3) * 32;
    const bool isW3 = warp >= 4;
    const int bOffBase = B_OFF + (isW3 ? 8192 : 0);

    float acc[2][8][4];
#pragma unroll
    for (int i = 0; i < 2; i++)
#pragma unroll
        for (int j = 0; j < 8; j++)
#pragma unroll
            for (int q = 0; q < 4; q++) acc[i][j][q] = 0.f;

#pragma unroll
    for (int pf = 0; pf < 2; pf++) {
        load_A(sb + pf * STG, g_Xf, CD, asrc, pf * 64, tid);
        load_B1(sb + pf * STG, e, n0, pf * 64, tid);
        CP_COMMIT();
    }
    for (int ch = 0; ch < 16; ch++) {
        PIPE_WAIT(ch);
        __syncthreads();
        if (ch + 2 < 16) {
            uint32_t nb = sb + ((ch + 2) % 3) * STG;
            load_A(nb, g_Xf, CD, asrc, (ch + 2) * 64, tid);
            load_B1(nb, e, n0, (ch + 2) * 64, tid);
            CP_COMMIT();
        }
        chunk_mma(sb + (ch % 3) * STG, bOffBase, 0, mb, lane, acc);
    }
    __syncthreads();

    // epilogue: exchange P1/P3 via smem, gelu*mul, store H fp16
    float* P1 = (float*)dsm;
    float* P3 = (float*)(dsm + 33792);
    float* myP = isW3 ? P3 : P1;
#pragma unroll
    for (int mi = 0; mi < 2; mi++)
#pragma unroll
        for (int ni = 0; ni < 8; ni++) {
            int m = mb + mi * 16 + (lane >> 2);
            int n = ni * 8 + (lane & 3) * 2;
            myP[m * 66 + n]       = acc[mi][ni][0];
            myP[m * 66 + n + 1]   = acc[mi][ni][1];
            myP[(m+8) * 66 + n]   = acc[mi][ni][2];
            myP[(m+8) * 66 + n+1] = acc[mi][ni][3];
        }
    __syncthreads();
    for (int idx = tid; idx < 128 * 64; idx += 256) {
        int m = idx >> 6, n = idx & 63;
        int entry = rows[m];
        if (entry < 0) continue;
        float d1 = P1[m * 66 + n];
        float d3 = P3[m * 66 + n];
        float gl = 0.5f * d1 * (1.f + erff(d1 * 0.70710678118654752f)) * d3;
        g_Hf[(size_t)entry * FD + n0 + n] = __float2half_rn(gl);
    }
}

// GEMM2: 128 rows x 128 out cols; warp grid 4(m) x 2(n)
__global__ __launch_bounds__(256, 2) void gemm2_mma() {
    int e, m0;
    if (!decode_tile(blockIdx.y, e, m0)) return;
    extern __shared__ char dsm[];
    __shared__ int rows[128];
    __shared__ int asrc[128];
    __shared__ float wts[128];

    const int tid = threadIdx.x, warp = tid >> 5, lane = tid & 31;
    const int ne = g_cnt[e];
    const int n0 = blockIdx.x * 128;

    if (tid < 128) {
        int i = m0 + tid;
        int ic = (i < ne) ? i : ne - 1;
        int entry = g_list[e * TT + ic];
        rows[tid] = (i < ne) ? entry : -1;
        asrc[tid] = entry;
        wts[tid] = (i < ne) ? g_wt[entry] : 0.f;
    }
    __syncthreads();

    const uint32_t sb = smem_u32(dsm);
    const int mb = (warp >> 1) * 32;
    const int nb = (warp & 1) * 64;

    float acc[2][8][4];
#pragma unroll
    for (int i = 0; i < 2; i++)
#pragma unroll
        for (int j = 0; j < 8; j++)
#pragma unroll
            for (int q = 0; q < 4; q++) acc[i][j][q] = 0.f;

#pragma unroll
    for (int pf = 0; pf < 2; pf++) {
        load_A(sb + pf * STG, g_Hf, FD, asrc, pf * 64, tid);
        load_B2(sb + pf * STG, e, n0, pf * 64, tid);
        CP_COMMIT();
    }
    for (int ch = 0; ch < 16; ch++) {
        PIPE_WAIT(ch);
        __syncthreads();
        if (ch + 2 < 16) {
            uint32_t nbuf = sb + ((ch + 2) % 3) * STG;
            load_A(nbuf, g_Hf, FD, asrc, (ch + 2) * 64, tid);
            load_B2(nbuf, e, n0, (ch + 2) * 64, tid);
            CP_COMMIT();
        }
        chunk_mma(sb + (ch % 3) * STG, B_OFF, nb, mb, lane, acc);
    }

    // epilogue: scale by routing weight, store Y fp16
#pragma unroll
    for (int mi = 0; mi < 2; mi++) {
        int mB = mb + mi * 16 + (lane >> 2);
#pragma unroll
        for (int half = 0; half < 2; half++) {
            int m = mB + half * 8;
            int entry = rows[m];
            if (entry < 0) continue;
            float w = wts[m];
            __half* yr = g_Yf + (size_t)entry * CD + n0 + nb;
#pragma unroll
            for (int ni = 0; ni < 8; ni++) {
                int n = ni * 8 + (lane & 3) * 2;
                *(__half2*)(yr + n) = __floats2half2_rn(w * acc[mi][ni][half * 2],
                                                        w * acc[mi][ni][half * 2 + 1]);
            }
        }
    }
}

// sum two slots (fp16), transpose back to NCHW fp32
__global__ __launch_bounds__(256) void combine_out_kernel(float* __restrict__ out) {
    __shared__ float tile[32][33];
    const int b = blockIdx.z, c0 = blockIdx.y * 32, s0 = blockIdx.x * 32;
    const int tx = threadIdx.x, ty = threadIdx.y;
#pragma unroll
    for (int r = 0; r < 4; r++) {
        int ss = ty + r * 8;
        size_t t2 = (size_t)(b * HWD + s0 + ss) * 2;
        tile[ss][tx] = __half2float(g_Yf[t2 * CD + c0 + tx]) +
                       __half2float(g_Yf[(t2 + 1) * CD + c0 + tx]);
    }
    __syncthreads();
#pragma unroll
    for (int r = 0; r < 4; r++) {
        int cc = ty + r * 8;
        out[((size_t)(b * CD + c0 + cc)) * HWD + s0 + tx] = tile[tx][cc];
    }
}

// ------------------------------------------------------------------
extern "C" void kernel_launch(void* const* d_in, const int* in_sizes, int n_in,
                              void* d_out, int out_size) {
    const float* hs   = (const float*)d_in[0];
    const float* gate = (const float*)d_in[1];
    const float* w1   = (const float*)d_in[2];
    const float* w2   = (const float*)d_in[3];
    const float* w3   = (const float*)d_in[4];
    float* out = (float*)d_out;

    cudaFuncSetAttribute(gemm1_mma, cudaFuncAttributeMaxDynamicSharedMemorySize, DSM);
    cudaFuncSetAttribute(gemm2_mma, cudaFuncAttributeMaxDynamicSharedMemorySize, DSM);

    reset_kernel<<<1, 32>>>();
    router_kernel<<<TT / 32, 256>>>(hs, gate);
    transpose_pack_kernel<<<dim3(HWD / 32, CD / 32, BD), dim3(32, 8)>>>(hs);
    prep_all<<<dim3(NE * FD * CD / 4 / 256, 3), 256>>>(w1, w3, w2);
    gemm1_mma<<<dim3(FD / 64, 136), 256, DSM>>>();
    gemm2_mma<<<dim3(CD / 128, 136), 256, DSM>>>();
    combine_out_kernel<<<dim3(HWD / 32, CD / 32, BD), dim3(32, 8)>>>(out);
}

// round 16
// speedup vs baseline: 1.2031x; 1.0108x over previous
#include <cuda_runtime.h>
#include <cuda_fp16.h>
#include <math.h>
#include <stdint.h>

#define TT   8192
#define CD   1024
#define FD   1024
#define NE   8
#define HWD  4096
#define BD   2
#define NENT (TT*2)

// ---------------- scratch (16B-aligned for cp.async / vector ld-st) ----------------
__device__ __align__(16) __half g_Xf [TT * CD];
__device__ __align__(16) __half g_W1 [NE * FD * CD];
__device__ __align__(16) __half g_W3 [NE * FD * CD];
__device__ __align__(16) __half g_W2 [NE * CD * FD];
__device__ __align__(16) __half g_Hf [NENT * FD];
__device__ __align__(16) __half g_Yf [NENT * CD];
__device__ __align__(16) float  g_wt [NENT];
__device__ int  g_cnt[NE];
__device__ __align__(16) int  g_list[NE * TT];

// ---------------- helpers ----------------
__device__ __forceinline__ uint32_t smem_u32(const void* p) {
    uint32_t a;
    asm("{ .reg .u64 t; cvta.to.shared.u64 t, %1; cvt.u32.u64 %0, t; }" : "=r"(a) : "l"(p));
    return a;
}
__device__ __forceinline__ void cp16(uint32_t dst, const void* src) {
    asm volatile("cp.async.cg.shared.global [%0], [%1], 16;" :: "r"(dst), "l"(src) : "memory");
}
#define CP_COMMIT() asm volatile("cp.async.commit_group;" ::: "memory")
#define CP_WAIT1()  asm volatile("cp.async.wait_group 1;" ::: "memory")
#define CP_WAIT0()  asm volatile("cp.async.wait_group 0;" ::: "memory")
#define PIPE_WAIT(ch) do { if ((ch) < 15) { CP_WAIT1(); } else { CP_WAIT0(); } } while (0)

// SW128 swizzle: conflict-free ldmatrix on 128B rows, composes with 16B cp.async
__device__ __forceinline__ uint32_t sw128(uint32_t o) { return o ^ ((o >> 3) & 0x70); }

__device__ __forceinline__ void ldsm4(uint32_t* r, uint32_t a) {
    asm volatile("ldmatrix.sync.aligned.m8n8.x4.shared.b16 {%0,%1,%2,%3}, [%4];"
        : "=r"(r[0]), "=r"(r[1]), "=r"(r[2]), "=r"(r[3]) : "r"(a));
}
__device__ __forceinline__ void mma_f16(float* c, const uint32_t* a, const uint32_t* b) {
    asm volatile(
        "mma.sync.aligned.m16n8k16.row.col.f32.f16.f16.f32 "
        "{%0,%1,%2,%3}, {%4,%5,%6,%7}, {%8,%9}, {%0,%1,%2,%3};"
        : "+f"(c[0]), "+f"(c[1]), "+f"(c[2]), "+f"(c[3])
        : "r"(a[0]), "r"(a[1]), "r"(a[2]), "r"(a[3]), "r"(b[0]), "r"(b[1]));
}

// decode m-tile index -> (expert, m0); 8-iter scan over g_cnt. Returns false if mt OOB.
__device__ __forceinline__ bool decode_tile(int mt, int& e_out, int& m0_out) {
    int acc = 0;
#pragma unroll
    for (int e = 0; e < NE; e++) {
        int nt_e = (g_cnt[e] + 127) >> 7;
        if (mt < acc + nt_e) { e_out = e; m0_out = (mt - acc) * 128; return true; }
        acc += nt_e;
    }
    return false;
}

// smem stage layout (bytes), K-chunk 64, stage 32768, THREE stages
#define A_OFF 0
#define B_OFF 16384
#define STG   32768
#define DSM   (3*STG)   // 98304

// ------------------------------------------------------------------
__global__ void reset_kernel() { if (threadIdx.x < NE) g_cnt[threadIdx.x] = 0; }

// NCHW -> [T,C] fp16 plane only
__global__ __launch_bounds__(256) void transpose_pack_kernel(const float* __restrict__ hs) {
    __shared__ float tile[32][33];
    const int b = blockIdx.z, c0 = blockIdx.y * 32, s0 = blockIdx.x * 32;
    const int tx = threadIdx.x, ty = threadIdx.y;
#pragma unroll
    for (int r = 0; r < 4; r++) {
        int cc = ty + r * 8;
        tile[cc][tx] = hs[((size_t)(b * CD + c0 + cc)) * HWD + s0 + tx];
    }
    __syncthreads();
#pragma unroll
    for (int r = 0; r < 4; r++) {
        int ss = ty + r * 8;
        size_t idx = ((size_t)(b * HWD + s0 + ss)) * CD + c0 + tx;
        g_Xf[idx] = __float2half_rn(tile[tx][ss]);
    }
}

// weights -> fp16; 8 elements/thread: 2x float4 load, 1x uint4 (STG.128) store
__global__ __launch_bounds__(256) void prep_all(const float* __restrict__ w1,
                                                const float* __restrict__ w3,
                                                const float* __restrict__ w2) {
    const int which = blockIdx.y;
    const float* s = (which == 0) ? w1 : (which == 1) ? w3 : w2;
    __half* dh = (which == 0) ? g_W1 : (which == 1) ? g_W3 : g_W2;
    size_t i = ((size_t)blockIdx.x * 256 + threadIdx.x) * 8;
    float4 v0 = *(const float4*)(s + i);
    float4 v1 = *(const float4*)(s + i + 4);
    __half hbuf[8] = { __float2half_rn(v0.x), __float2half_rn(v0.y),
                       __float2half_rn(v0.z), __float2half_rn(v0.w),
                       __float2half_rn(v1.x), __float2half_rn(v1.y),
                       __float2half_rn(v1.z), __float2half_rn(v1.w) };
    *(uint4*)(dh + i) = *(uint4*)hbuf;
}

// router v3: NCHW-direct, 32 tokens/block, warp = 128-channel slice, fp32 math
__global__ __launch_bounds__(256) void router_kernel(const float* __restrict__ hs,
                                                     const float* __restrict__ gw) {
    __shared__ float sg[NE * CD];
    __shared__ float part[8][32][NE];
    const int tid = threadIdx.x;
    for (int i = tid; i < NE * CD; i += 256) sg[i] = gw[i];
    __syncthreads();

    const int warp = tid >> 5, lane = tid & 31;
    const int tok0 = blockIdx.x * 32;
    const int b = tok0 >> 12;
    const int s = (tok0 & (HWD - 1)) + lane;
    const float* src = hs + ((size_t)b * CD + warp * 128) * HWD + s;
    const float* gq  = sg + warp * 128;

    float acc[NE];
#pragma unroll
    for (int e = 0; e < NE; e++) acc[e] = 0.f;
    for (int c = 0; c < 128; c += 4) {
        float x0 = src[(size_t)(c + 0) * HWD];
        float x1 = src[(size_t)(c + 1) * HWD];
        float x2 = src[(size_t)(c + 2) * HWD];
        float x3 = src[(size_t)(c + 3) * HWD];
#pragma unroll
        for (int e = 0; e < NE; e++) {
            acc[e] = fmaf(x0, gq[e * CD + c + 0], acc[e]);
            acc[e] = fmaf(x1, gq[e * CD + c + 1], acc[e]);
            acc[e] = fmaf(x2, gq[e * CD + c + 2], acc[e]);
            acc[e] = fmaf(x3, gq[e * CD + c + 3], acc[e]);
        }
    }
#pragma unroll
    for (int e = 0; e < NE; e++) part[warp][lane][e] = acc[e];
    __syncthreads();

    if (tid < 32) {
        float p[NE];
#pragma unroll
        for (int e = 0; e < NE; e++) {
            float v = 0.f;
#pragma unroll
            for (int w = 0; w < 8; w++) v += part[w][tid][e];
            p[e] = v;
        }
        float mx = p[0];
#pragma unroll
        for (int e = 1; e < NE; e++) mx = fmaxf(mx, p[e]);
#pragma unroll
        for (int e = 0; e < NE; e++) p[e] = expf(p[e] - mx);
        int i0 = 0; float b0 = p[0];
#pragma unroll
        for (int e = 1; e < NE; e++) if (p[e] > b0) { b0 = p[e]; i0 = e; }
        int i1 = (i0 == 0) ? 1 : 0; float b1 = p[i1];
#pragma unroll
        for (int e = 0; e < NE; e++)
            if (e != i0 && p[e] > b1) { b1 = p[e]; i1 = e; }
        float inv = 1.f / (b0 + b1);
        const int t = tok0 + tid;
        g_wt[t * 2 + 0] = b0 * inv;
        g_wt[t * 2 + 1] = b1 * inv;
        int p0 = atomicAdd(&g_cnt[i0], 1);
        g_list[i0 * TT + p0] = t * 2 + 0;
        int p1 = atomicAdd(&g_cnt[i1], 1);
        g_list[i1 * TT + p1] = t * 2 + 1;
    }
}

// ---- tile loaders (cp.async), K-chunk 64, SW128 swizzled smem ----
__device__ __forceinline__ void load_A(uint32_t sbase, const __half* __restrict__ src0,
                                       int kstride, const int* asrc, int k0, int tid) {
#pragma unroll
    for (int i = 0; i < 4; i++) {
        int seg = tid + i * 256;
        int row = seg >> 3, q = seg & 7;
        const __half* src = src0 + (size_t)asrc[row] * kstride + k0 + q * 8;
        cp16(sbase + A_OFF + sw128((uint32_t)(row * 128 + q * 16)), src);
    }
}
__device__ __forceinline__ void load_B1(uint32_t sbase, int e, int n0, int k0, int tid) {
#pragma unroll
    for (int i = 0; i < 4; i++) {
        int seg = tid + i * 256;
        int mat = seg >> 9;
        int rem = seg & 511;
        int row = rem >> 3, q = rem & 7;
        const __half* base = mat ? g_W3 : g_W1;
        const __half* src = base + ((size_t)e * FD + n0 + row) * CD + k0 + q * 8;
        cp16(sbase + B_OFF + mat * 8192 + sw128((uint32_t)(row * 128 + q * 16)), src);
    }
}
__device__ __forceinline__ void load_B2(uint32_t sbase, int e, int n0, int k0, int tid) {
#pragma unroll
    for (int i = 0; i < 4; i++) {
        int seg = tid + i * 256;
        int row = (seg & 1023) >> 3, q = seg & 7;
        const __half* src = g_W2 + ((size_t)e * CD + n0 + row) * FD + k0 + q * 8;
        cp16(sbase + B_OFF + sw128((uint32_t)(row * 128 + q * 16)), src);
    }
}

// ---- warp compute for one 64-k chunk: m32 x n64, single plane ----
__device__ __forceinline__ void chunk_mma(uint32_t sbase, int bOffBase, int bRowBase,
                                          int mb, int lane, float acc[2][8][4]) {
    const int arow = lane & 15, akoff = ((lane >> 4) & 1) * 8;
    const int brow = ((lane >> 4) & 1) * 8 + (lane & 7);
    const int bkoff = ((lane >> 3) & 1) * 8;
#pragma unroll
    for (int kb = 0; kb < 64; kb += 16) {
        uint32_t a[2][4];
#pragma unroll
        for (int mi = 0; mi < 2; mi++) {
            uint32_t off = sw128((uint32_t)((mb + mi * 16 + arow) * 128 + (kb + akoff) * 2));
            ldsm4(a[mi], sbase + A_OFF + off);
        }
        uint32_t bf[8][2];
#pragma unroll
        for (int n4 = 0; n4 < 4; n4++) {
            uint32_t off = sw128((uint32_t)((bRowBase + n4 * 16 + brow) * 128 + (kb + bkoff) * 2));
            uint32_t t[4];
            ldsm4(t, sbase + bOffBase + off);
            bf[2*n4][0]=t[0]; bf[2*n4][1]=t[1]; bf[2*n4+1][0]=t[2]; bf[2*n4+1][1]=t[3];
        }
#pragma unroll
        for (int mi = 0; mi < 2; mi++)
#pragma unroll
            for (int ni = 0; ni < 8; ni++)
                mma_f16(acc[mi][ni], a[mi], bf[ni]);
    }
}

// ------------------------------------------------------------------
// GEMM1: 128 rows x 64 ffn cols; warps 0-3 -> W1, warps 4-7 -> W3
__global__ __launch_bounds__(256, 2) void gemm1_mma() {
    int e, m0;
    if (!decode_tile(blockIdx.y, e, m0)) return;
    extern __shared__ char dsm[];
    __shared__ int rows[128];
    __shared__ int asrc[128];

    const int tid = threadIdx.x, warp = tid >> 5, lane = tid & 31;
    const int ne = g_cnt[e];
    const int n0 = blockIdx.x * 64;

    if (tid < 128) {
        int i = m0 + tid;
        int ic = (i < ne) ? i : ne - 1;
        int entry = g_list[e * TT + ic];
        rows[tid] = (i < ne) ? entry : -1;
        asrc[tid] = entry >> 1;
    }
    __syncthreads();

    const uint32_t sb = smem_u32(dsm);
    const int mb = (warp & 3) * 32;
    const bool isW3 = warp >= 4;
    const int bOffBase = B_OFF + (isW3 ? 8192 : 0);

    float acc[2][8][4];
#pragma unroll
    for (int i = 0; i < 2; i++)
#pragma unroll
        for (int j = 0; j < 8; j++)
#pragma unroll
            for (int q = 0; q < 4; q++) acc[i][j][q] = 0.f;

#pragma unroll
    for (int pf = 0; pf < 2; pf++) {
        load_A(sb + pf * STG, g_Xf, CD, asrc, pf * 64, tid);
        load_B1(sb + pf * STG, e, n0, pf * 64, tid);
        CP_COMMIT();
    }
    for (int ch = 0; ch < 16; ch++) {
        PIPE_WAIT(ch);
        __syncthreads();
        if (ch + 2 < 16) {
            uint32_t nb = sb + ((ch + 2) % 3) * STG;
            load_A(nb, g_Xf, CD, asrc, (ch + 2) * 64, tid);
            load_B1(nb, e, n0, (ch + 2) * 64, tid);
            CP_COMMIT();
        }
        chunk_mma(sb + (ch % 3) * STG, bOffBase, 0, mb, lane, acc);
    }
    __syncthreads();

    // epilogue: exchange P1/P3 via smem, gelu*mul, store H fp16
    float* P1 = (float*)dsm;
    float* P3 = (float*)(dsm + 33792);
    float* myP = isW3 ? P3 : P1;
#pragma unroll
    for (int mi = 0; mi < 2; mi++)
#pragma unroll
        for (int ni = 0; ni < 8; ni++) {
            int m = mb + mi * 16 + (lane >> 2);
            int n = ni * 8 + (lane & 3) * 2;
            myP[m * 66 + n]       = acc[mi][ni][0];
            myP[m * 66 + n + 1]   = acc[mi][ni][1];
            myP[(m+8) * 66 + n]   = acc[mi][ni][2];
            myP[(m+8) * 66 + n+1] = acc[mi][ni][3];
        }
    __syncthreads();
    for (int idx = tid; idx < 128 * 64; idx += 256) {
        int m = idx >> 6, n = idx & 63;
        int entry = rows[m];
        if (entry < 0) continue;
        float d1 = P1[m * 66 + n];
        float d3 = P3[m * 66 + n];
        float gl = 0.5f * d1 * (1.f + erff(d1 * 0.70710678118654752f)) * d3;
        g_Hf[(size_t)entry * FD + n0 + n] = __float2half_rn(gl);
    }
}

// GEMM2: 128 rows x 128 out cols; warp grid 4(m) x 2(n)
__global__ __launch_bounds__(256, 2) void gemm2_mma() {
    int e, m0;
    if (!decode_tile(blockIdx.y, e, m0)) return;
    extern __shared__ char dsm[];
    __shared__ int rows[128];
    __shared__ int asrc[128];
    __shared__ float wts[128];

    const int tid = threadIdx.x, warp = tid >> 5, lane = tid & 31;
    const int ne = g_cnt[e];
    const int n0 = blockIdx.x * 128;

    if (tid < 128) {
        int i = m0 + tid;
        int ic = (i < ne) ? i : ne - 1;
        int entry = g_list[e * TT + ic];
        rows[tid] = (i < ne) ? entry : -1;
        asrc[tid] = entry;
        wts[tid] = (i < ne) ? g_wt[entry] : 0.f;
    }
    __syncthreads();

    const uint32_t sb = smem_u32(dsm);
    const int mb = (warp >> 1) * 32;
    const int nb = (warp & 1) * 64;

    float acc[2][8][4];
#pragma unroll
    for (int i = 0; i < 2; i++)
#pragma unroll
        for (int j = 0; j < 8; j++)
#pragma unroll
            for (int q = 0; q < 4; q++) acc[i][j][q] = 0.f;

#pragma unroll
    for (int pf = 0; pf < 2; pf++) {
        load_A(sb + pf * STG, g_Hf, FD, asrc, pf * 64, tid);
        load_B2(sb + pf * STG, e, n0, pf * 64, tid);
        CP_COMMIT();
    }
    for (int ch = 0; ch < 16; ch++) {
        PIPE_WAIT(ch);
        __syncthreads();
        if (ch + 2 < 16) {
            uint32_t nbuf = sb + ((ch + 2) % 3) * STG;
            load_A(nbuf, g_Hf, FD, asrc, (ch + 2) * 64, tid);
            load_B2(nbuf, e, n0, (ch + 2) * 64, tid);
            CP_COMMIT();
        }
        chunk_mma(sb + (ch % 3) * STG, B_OFF, nb, mb, lane, acc);
    }

    // epilogue: scale by routing weight, store Y fp16
#pragma unroll
    for (int mi = 0; mi < 2; mi++) {
        int mB = mb + mi * 16 + (lane >> 2);
#pragma unroll
        for (int half = 0; half < 2; half++) {
            int m = mB + half * 8;
            int entry = rows[m];
            if (entry < 0) continue;
            float w = wts[m];
            __half* yr = g_Yf + (size_t)entry * CD + n0 + nb;
#pragma unroll
            for (int ni = 0; ni < 8; ni++) {
                int n = ni * 8 + (lane & 3) * 2;
                *(__half2*)(yr + n) = __floats2half2_rn(w * acc[mi][ni][half * 2],
                                                        w * acc[mi][ni][half * 2 + 1]);
            }
        }
    }
}

// combine v2: half2 reads (128B/warp), 64-channel x 32-spatial tiles
__global__ __launch_bounds__(256) void combine_out_kernel(float* __restrict__ out) {
    __shared__ float tile[64][33];
    const int b = blockIdx.z, c0 = blockIdx.y * 64, s0 = blockIdx.x * 32;
    const int tx = threadIdx.x, ty = threadIdx.y;
    // read: token = s0+ss (spatial), 64 channels via half2; each thread 2 channels
#pragma unroll
    for (int r = 0; r < 4; r++) {
        int ss = ty + r * 8;
        size_t t2 = (size_t)(b * HWD + s0 + ss) * 2;
        __half2 v0 = *(const __half2*)(g_Yf + t2 * CD + c0 + tx * 2);
        __half2 v1 = *(const __half2*)(g_Yf + (t2 + 1) * CD + c0 + tx * 2);
        float2 f0 = __half22float2(v0), f1 = __half22float2(v1);
        tile[tx * 2 + 0][ss] = f0.x + f1.x;
        tile[tx * 2 + 1][ss] = f0.y + f1.y;
    }
    __syncthreads();
    // write: out[b][c][s], 32-wide coalesced rows, 8 rows per ty pass
#pragma unroll
    for (int r = 0; r < 8; r++) {
        int cc = ty + r * 8;
        out[((size_t)(b * CD + c0 + cc)) * HWD + s0 + tx] = tile[cc][tx];
    }
}

// ------------------------------------------------------------------
extern "C" void kernel_launch(void* const* d_in, const int* in_sizes, int n_in,
                              void* d_out, int out_size) {
    const float* hs   = (const float*)d_in[0];
    const float* gate = (const float*)d_in[1];
    const float* w1   = (const float*)d_in[2];
    const float* w2   = (const float*)d_in[3];
    const float* w3   = (const float*)d_in[4];
    float* out = (float*)d_out;

    cudaFuncSetAttribute(gemm1_mma, cudaFuncAttributeMaxDynamicSharedMemorySize, DSM);
    cudaFuncSetAttribute(gemm2_mma, cudaFuncAttributeMaxDynamicSharedMemorySize, DSM);

    reset_kernel<<<1, 32>>>();
    router_kernel<<<TT / 32, 256>>>(hs, gate);
    transpose_pack_kernel<<<dim3(HWD / 32, CD / 32, BD), dim3(32, 8)>>>(hs);
    prep_all<<<dim3(NE * FD * CD / 8 / 256, 3), 256>>>(w1, w3, w2);
    gemm1_mma<<<dim3(FD / 64, 136), 256, DSM>>>();
    gemm2_mma<<<dim3(CD / 128, 136), 256, DSM>>>();
    combine_out_kernel<<<dim3(HWD / 32, CD / 64, BD), dim3(32, 8)>>>(out);
}